// round 7
// baseline (speedup 1.0000x reference)
#include <cuda_runtime.h>
#include <cuda_bf16.h>
#include <cstdint>

// ===========================================================================
// Problem constants
// ===========================================================================
#define D        144
#define NROWS    4096
#define NCODES   50257
#define ZQ_ELEMS (NROWS * D)

#define BM       128                        // rows per CTA
#define BN       64                         // codes per tile iteration
#define TILES    ((NCODES + BN - 1) / BN)   // 786
#define NSPLIT   9
#define TPS      ((TILES + NSPLIT - 1) / NSPLIT) // 88

#define CAP      2048                       // candidate slots per row
#define CAPW     4e-5f                      // capture window (dot units)
#define ASTR     152                        // A smem row stride (bf16 elems)
#define BSTR     152                        // B smem row stride (bf16 elems)

// SMEM layout (bytes): A tile + 3-stage B ring
#define A_BYTES  (BM * ASTR * 2)            // 38912
#define B_BYTES  (BN * BSTR * 2)            // 19456
#define SMEM_TOTAL (A_BYTES + 3 * B_BYTES)  // 97280

// ===========================================================================
// Global scratch (device globals only — no cudaMalloc)
// ===========================================================================
__device__ unsigned long long g_best[NROWS];
__device__ float    g_nrm[NCODES];
__device__ float    g_zn[NROWS];
__device__ float    g_part[NROWS];
__device__ int      g_cnt[NROWS];
__device__ unsigned g_cand[(size_t)NROWS * CAP];
__device__ __align__(16) __nv_bfloat16 g_embh[(size_t)NCODES * D];

__device__ __forceinline__ unsigned ordered_bits(float s) {
    unsigned b = __float_as_uint(s);
    return b ^ ((unsigned)((int)b >> 31) | 0x80000000u);
}
__device__ __forceinline__ unsigned pack_bf16x2(float lo, float hi) {
    __nv_bfloat162 h = __floats2bfloat162_rn(lo, hi);
    return *(unsigned*)&h;
}
__device__ __forceinline__ uint32_t smem_u32(const void* p) {
    uint32_t a;
    asm("{ .reg .u64 t; cvta.to.shared.u64 t, %1; cvt.u32.u64 %0, t; }"
        : "=r"(a) : "l"(p));
    return a;
}
__device__ __forceinline__ void ldsm4(unsigned a[4], unsigned addr) {
    asm volatile("ldmatrix.sync.aligned.m8n8.x4.shared.b16 {%0,%1,%2,%3}, [%4];"
                 : "=r"(a[0]), "=r"(a[1]), "=r"(a[2]), "=r"(a[3]) : "r"(addr));
}
__device__ __forceinline__ void mma16816(float c[4], const unsigned a[4],
                                         const unsigned b0, const unsigned b1) {
    asm volatile(
        "mma.sync.aligned.m16n8k16.row.col.f32.bf16.bf16.f32 "
        "{%0,%1,%2,%3}, {%4,%5,%6,%7}, {%8,%9}, {%0,%1,%2,%3};"
        : "+f"(c[0]), "+f"(c[1]), "+f"(c[2]), "+f"(c[3])
        : "r"(a[0]), "r"(a[1]), "r"(a[2]), "r"(a[3]), "r"(b0), "r"(b1));
}
#define CP_ASYNC16(s, g) \
    asm volatile("cp.async.cg.shared.global [%0], [%1], 16;" \
                 :: "r"(s), "l"(g) : "memory")
#define CP_COMMIT() asm volatile("cp.async.commit_group;" ::: "memory")
#define CP_WAIT(N)  asm volatile("cp.async.wait_group %0;" :: "n"(N) : "memory")

// ===========================================================================
// Kernel 1: norms, bf16 emb copy, scratch reset (R2-identical norm arithmetic)
// ===========================================================================
__global__ void prep_kernel(const float* __restrict__ z,
                            const float* __restrict__ emb) {
    int t = blockIdx.x * 256 + threadIdx.x;
    if (t < NROWS) {
        g_best[t] = 0xFFFFFFFFFFFFFFFFull;
        g_cnt[t] = 0;
        const float4* p = (const float4*)(z + (size_t)t * D);
        float s = 0.f;
        #pragma unroll
        for (int i = 0; i < 36; i++) {
            float4 v = p[i];
            s += v.x * v.x + v.y * v.y + v.z * v.z + v.w * v.w;
        }
        g_zn[t] = s;
    }
    if (t < NCODES) {
        const float4* p = (const float4*)(emb + (size_t)t * D);
        uint2* dst = (uint2*)(g_embh + (size_t)t * D);
        float s = 0.f;
        #pragma unroll
        for (int i = 0; i < 36; i++) {
            float4 v = p[i];
            s += v.x * v.x + v.y * v.y + v.z * v.z + v.w * v.w;
            dst[i] = make_uint2(pack_bf16x2(v.x, v.y), pack_bf16x2(v.z, v.w));
        }
        g_nrm[t] = s;
    }
}

// ===========================================================================
// Kernel 2: bf16 mma.sync screening; B via 3-stage cp.async ring.
// grid(32, 9), 256 threads (warps 2m x 4n, warp tile 64x16), 2 CTAs/SM
// ===========================================================================
__device__ __forceinline__ void stageB(unsigned bdst, int tile, int tid) {
    int code = tid >> 2;                 // 0..63
    int q    = tid & 3;
    int gc = tile * BN + code;
    if (gc > NCODES - 1) gc = NCODES - 1;   // clamp: real-code data, safe
    const char* g = (const char*)(g_embh + (size_t)gc * D);
    unsigned srow = bdst + (unsigned)(code * BSTR) * 2;
    #pragma unroll
    for (int j = 0; j < 4; j++)
        CP_ASYNC16(srow + (q + 4 * j) * 16, g + (q + 4 * j) * 16);
    if (q < 2)
        CP_ASYNC16(srow + (16 + q) * 16, g + (16 + q) * 16);
}

__global__ void __launch_bounds__(256, 2)
screen_kernel(const float* __restrict__ z) {
    extern __shared__ __nv_bfloat16 smem[];
    __nv_bfloat16* As = smem;

    const int tid  = threadIdx.x;
    const int lane = tid & 31;
    const int wid  = tid >> 5;
    const int mwarp = wid >> 2;       // 0..1
    const int nwarp = wid & 3;        // 0..3
    const int row0 = blockIdx.x * BM;

    const unsigned asbase = smem_u32(As);
    const unsigned bbase[3] = { asbase + A_BYTES,
                                asbase + A_BYTES + B_BYTES,
                                asbase + A_BYTES + 2 * B_BYTES };

    // A tile: z -> bf16 smem (row-major, stride ASTR). 2 threads per row.
    {
        int row = tid >> 1, half = tid & 1;
        const float4* src = (const float4*)(z + (size_t)(row0 + row) * D + half * 72);
        unsigned eo = row * ASTR + half * 72;
        #pragma unroll
        for (int j = 0; j < 18; j++) {
            float4 v = src[j];
            *(uint2*)(As + eo + j * 4) =
                make_uint2(pack_bf16x2(v.x, v.y), pack_bf16x2(v.z, v.w));
        }
    }

    const int tile0 = blockIdx.y * TPS;
    const int tile1 = min(tile0 + TPS, TILES);

    // Prologue: stage up to 2 tiles ahead
    stageB(bbase[0], tile0, tid);
    CP_COMMIT();
    if (tile0 + 1 < tile1) {
        stageB(bbase[1], tile0 + 1, tid);
        CP_COMMIT();
    }

    float rmax[8];
    #pragma unroll
    for (int i = 0; i < 8; i++) rmax[i] = __int_as_float(0xff800000);

    for (int ti = tile0; ti < tile1; ++ti) {
        const int it = ti - tile0;
        const unsigned bs = bbase[it % 3];
        const int c0 = ti * BN;

        if (ti + 1 < tile1) CP_WAIT(1); else CP_WAIT(0);
        __syncthreads();      // B_ti visible; everyone done reading B_{ti-1}

        if (ti + 2 < tile1) {
            stageB(bbase[(it + 2) % 3], ti + 2, tid);
            CP_COMMIT();
        }

        float acc[4][2][4];
        #pragma unroll
        for (int mt = 0; mt < 4; mt++)
            #pragma unroll
            for (int nt = 0; nt < 2; nt++)
                #pragma unroll
                for (int j = 0; j < 4; j++) acc[mt][nt][j] = 0.f;

        #pragma unroll
        for (int ks = 0; ks < 9; ks++) {
            unsigned a[4][4];
            #pragma unroll
            for (int mt = 0; mt < 4; mt++) {
                unsigned arow = mwarp * 64 + mt * 16 + (lane & 15);
                unsigned abyte = (arow * ASTR + ks * 16 + (lane >> 4) * 8) * 2;
                ldsm4(a[mt], asbase + abyte);
            }
            unsigned bfr[4];
            {
                unsigned brow = nwarp * 16 + ((lane >> 4) << 3) + (lane & 7);
                unsigned bcol = ks * 16 + (((lane >> 3) & 1) << 3);
                ldsm4(bfr, bs + (brow * BSTR + bcol) * 2);
            }
            #pragma unroll
            for (int mt = 0; mt < 4; mt++) {
                mma16816(acc[mt][0], a[mt], bfr[0], bfr[1]);
                mma16816(acc[mt][1], a[mt], bfr[2], bfr[3]);
            }
        }

        // Epilogue: per-row running max, then capture within window
        #pragma unroll
        for (int mt = 0; mt < 4; mt++) {
            #pragma unroll
            for (int nt = 0; nt < 2; nt++)
                #pragma unroll
                for (int j = 0; j < 4; j++) {
                    int h = j >> 1;
                    rmax[mt * 2 + h] = fmaxf(rmax[mt * 2 + h], acc[mt][nt][j]);
                }
            #pragma unroll
            for (int nt = 0; nt < 2; nt++)
                #pragma unroll
                for (int j = 0; j < 4; j++) {
                    int h = j >> 1;
                    float v = acc[mt][nt][j];
                    if (v >= rmax[mt * 2 + h] - CAPW) {
                        int c = c0 + nwarp * 16 + nt * 8 + (lane & 3) * 2 + (j & 1);
                        if (c < NCODES) {
                            int r = row0 + mwarp * 64 + mt * 16 + (lane >> 2) + h * 8;
                            int p = atomicAdd(&g_cnt[r], 1);
                            if (p < CAP) g_cand[(size_t)r * CAP + p] = (unsigned)c;
                        }
                    }
                }
        }
        // Pool rmax across the 4 lanes that share each row
        #pragma unroll
        for (int i = 0; i < 8; i++) {
            float o = __shfl_xor_sync(0xFFFFFFFFu, rmax[i], 1);
            rmax[i] = fmaxf(rmax[i], o);
            o = __shfl_xor_sync(0xFFFFFFFFu, rmax[i], 2);
            rmax[i] = fmaxf(rmax[i], o);
        }
    }
}

// ===========================================================================
// Kernel 3: exact fp32 rescore (bit-identical to R2 scoring semantics)
// ===========================================================================
__global__ void rescore_kernel(const float* __restrict__ z,
                               const float* __restrict__ emb) {
    const int row = blockIdx.x;
    __shared__ float zs[D];
    for (int k = threadIdx.x; k < D; k += 64) zs[k] = z[(size_t)row * D + k];
    __syncthreads();
    const float zn = g_zn[row];
    const int cnt = min(g_cnt[row], CAP);
    for (int i = threadIdx.x; i < cnt; i += 64) {
        unsigned c = g_cand[(size_t)row * CAP + i];
        const float4* e = (const float4*)(emb + (size_t)c * D);
        float acc = 0.f;
        #pragma unroll
        for (int q = 0; q < 36; q++) {
            float4 ev = e[q];
            acc = __fmaf_rn(zs[q * 4 + 0], ev.x, acc);
            acc = __fmaf_rn(zs[q * 4 + 1], ev.y, acc);
            acc = __fmaf_rn(zs[q * 4 + 2], ev.z, acc);
            acc = __fmaf_rn(zs[q * 4 + 3], ev.w, acc);
        }
        float t = __fadd_rn(zn, g_nrm[c]);
        float s = __fmaf_rn(acc, -2.f, t);
        unsigned long long key = ((unsigned long long)ordered_bits(s) << 32) | c;
        atomicMin(&g_best[row], key);
    }
}

// ===========================================================================
// Kernel 4: gather z_q, index, per-row squared-error partial
// ===========================================================================
__global__ void gather_kernel(const float* __restrict__ z,
                              const float* __restrict__ emb,
                              float* __restrict__ out) {
    const int row = blockIdx.x;
    const int tid = threadIdx.x;
    const unsigned idx = (unsigned)(g_best[row] & 0xFFFFFFFFull);
    const float* e  = emb + (size_t)idx * D;
    const float* zr = z + (size_t)row * D;
    float* o = out + (size_t)row * D;

    float s = 0.f;
    for (int d = tid; d < D; d += 128) {
        float q = e[d];
        o[d] = q;
        float df = q - zr[d];
        s += df * df;
    }
    #pragma unroll
    for (int off = 16; off >= 1; off >>= 1)
        s += __shfl_xor_sync(0xFFFFFFFFu, s, off);
    __shared__ float ws[4];
    if ((tid & 31) == 0) ws[tid >> 5] = s;
    __syncthreads();
    if (tid == 0) {
        g_part[row] = ws[0] + ws[1] + ws[2] + ws[3];
        out[ZQ_ELEMS + row] = (float)idx;
    }
}

// ===========================================================================
// Kernel 5: loss (deterministic reduction)
// ===========================================================================
__global__ void finalize_kernel(float* __restrict__ out, int out_size) {
    __shared__ float sh[256];
    float s = 0.f;
    for (int i = threadIdx.x; i < NROWS; i += 256) s += g_part[i];
    sh[threadIdx.x] = s;
    __syncthreads();
    for (int off = 128; off >= 1; off >>= 1) {
        if (threadIdx.x < off) sh[threadIdx.x] += sh[threadIdx.x + off];
        __syncthreads();
    }
    if (threadIdx.x == 0)
        out[out_size - 1] = sh[0] / (float)(ZQ_ELEMS);
}

// ===========================================================================
extern "C" void kernel_launch(void* const* d_in, const int* in_sizes, int n_in,
                              void* d_out, int out_size) {
    const float* z   = (const float*)d_in[0];
    const float* emb = (const float*)d_in[1];
    float* out = (float*)d_out;

    cudaFuncSetAttribute(screen_kernel,
                         cudaFuncAttributeMaxDynamicSharedMemorySize, SMEM_TOTAL);

    prep_kernel<<<(NCODES + 255) / 256, 256>>>(z, emb);
    screen_kernel<<<dim3(NROWS / BM, NSPLIT), 256, SMEM_TOTAL>>>(z);
    rescore_kernel<<<NROWS, 64>>>(z, emb);
    gather_kernel<<<NROWS, 128>>>(z, emb, out);
    finalize_kernel<<<1, 256>>>(out, out_size);
}

// round 8
// speedup vs baseline: 1.1982x; 1.1982x over previous
#include <cuda_runtime.h>
#include <cuda_bf16.h>
#include <cstdint>

// ===========================================================================
// Problem constants
// ===========================================================================
#define D        144
#define NROWS    4096
#define NCODES   50257
#define ZQ_ELEMS (NROWS * D)

#define BM       128                        // rows per CTA
#define BN       128                        // codes per tile iteration
#define TILES    ((NCODES + BN - 1) / BN)   // 393
#define NSPLIT   19
#define TPS      ((TILES + NSPLIT - 1) / NSPLIT) // 21

#define CAP      2048                       // candidate slots per row
#define CAPW     3e-5f                      // capture window (dot units)
#define ASTRIDE  152                        // A smem row stride (bf16 elems)

// ===========================================================================
// Global scratch (device globals only — no cudaMalloc)
// ===========================================================================
__device__ unsigned long long g_best[NROWS];
__device__ float    g_nrm[NCODES];
__device__ float    g_zn[NROWS];
__device__ float    g_part[NROWS];
__device__ int      g_cnt[NROWS];
__device__ unsigned g_cand[(size_t)NROWS * CAP];
__device__ __align__(16) __nv_bfloat16 g_embh[(size_t)NCODES * D];

__device__ __forceinline__ unsigned ordered_bits(float s) {
    unsigned b = __float_as_uint(s);
    return b ^ ((unsigned)((int)b >> 31) | 0x80000000u);
}
__device__ __forceinline__ unsigned pack_bf16x2(float lo, float hi) {
    __nv_bfloat162 h = __floats2bfloat162_rn(lo, hi);
    return *(unsigned*)&h;
}
__device__ __forceinline__ uint32_t smem_u32(const void* p) {
    uint32_t a;
    asm("{ .reg .u64 t; cvta.to.shared.u64 t, %1; cvt.u32.u64 %0, t; }"
        : "=r"(a) : "l"(p));
    return a;
}
__device__ __forceinline__ void ldsm4(unsigned a[4], unsigned addr) {
    asm volatile("ldmatrix.sync.aligned.m8n8.x4.shared.b16 {%0,%1,%2,%3}, [%4];"
                 : "=r"(a[0]), "=r"(a[1]), "=r"(a[2]), "=r"(a[3]) : "r"(addr));
}
__device__ __forceinline__ void mma16816(float c[4], const unsigned a[4],
                                         const unsigned b[2]) {
    asm volatile(
        "mma.sync.aligned.m16n8k16.row.col.f32.bf16.bf16.f32 "
        "{%0,%1,%2,%3}, {%4,%5,%6,%7}, {%8,%9}, {%0,%1,%2,%3};"
        : "+f"(c[0]), "+f"(c[1]), "+f"(c[2]), "+f"(c[3])
        : "r"(a[0]), "r"(a[1]), "r"(a[2]), "r"(a[3]), "r"(b[0]), "r"(b[1]));
}

// ===========================================================================
// Kernel 1: norms, bf16 emb copy, scratch reset (R2-identical norm arithmetic)
// ===========================================================================
__global__ void prep_kernel(const float* __restrict__ z,
                            const float* __restrict__ emb) {
    int t = blockIdx.x * 256 + threadIdx.x;
    if (t < NROWS) {
        g_best[t] = 0xFFFFFFFFFFFFFFFFull;
        g_cnt[t] = 0;
        const float4* p = (const float4*)(z + (size_t)t * D);
        float s = 0.f;
        #pragma unroll
        for (int i = 0; i < 36; i++) {
            float4 v = p[i];
            s += v.x * v.x + v.y * v.y + v.z * v.z + v.w * v.w;
        }
        g_zn[t] = s;
    }
    if (t < NCODES) {
        const float4* p = (const float4*)(emb + (size_t)t * D);
        uint2* dst = (uint2*)(g_embh + (size_t)t * D);
        float s = 0.f;
        #pragma unroll
        for (int i = 0; i < 36; i++) {
            float4 v = p[i];
            s += v.x * v.x + v.y * v.y + v.z * v.z + v.w * v.w;
            dst[i] = make_uint2(pack_bf16x2(v.x, v.y), pack_bf16x2(v.z, v.w));
        }
        g_nrm[t] = s;
    }
}

// ===========================================================================
// Kernel 2: bf16 mma.sync screening — barrier-free mainloop (R4 structure)
// grid(32, 19), 256 threads (warps 2m x 4n, warp tile 64x32), 2 CTAs/SM
// ===========================================================================
__device__ __forceinline__ void loadB(unsigned b[4][2], int c0, int ks,
                                      int nwarp, int lane) {
    #pragma unroll
    for (int nt = 0; nt < 4; nt++) {
        int code = c0 + nwarp * 32 + nt * 8 + (lane >> 2);
        if (code < NCODES) {
            const __nv_bfloat16* p =
                g_embh + (size_t)code * D + ks * 16 + (lane & 3) * 2;
            b[nt][0] = *(const unsigned*)p;
            b[nt][1] = *(const unsigned*)(p + 8);
        } else {
            b[nt][0] = 0u; b[nt][1] = 0u;
        }
    }
}

__global__ void __launch_bounds__(256, 2)
screen_kernel(const float* __restrict__ z) {
    __shared__ __nv_bfloat16 As[BM * ASTRIDE];

    const int tid  = threadIdx.x;
    const int lane = tid & 31;
    const int wid  = tid >> 5;
    const int mwarp = wid >> 2;       // 0..1
    const int nwarp = wid & 3;        // 0..3
    const int row0 = blockIdx.x * BM;

    // Load z tile -> bf16 smem (row-major, stride 152). 2 threads per row.
    {
        int row = tid >> 1, half = tid & 1;
        const float4* src = (const float4*)(z + (size_t)(row0 + row) * D + half * 72);
        unsigned eo = row * ASTRIDE + half * 72;
        #pragma unroll
        for (int j = 0; j < 18; j++) {
            float4 v = src[j];
            *(uint2*)(As + eo + j * 4) =
                make_uint2(pack_bf16x2(v.x, v.y), pack_bf16x2(v.z, v.w));
        }
    }
    __syncthreads();

    const unsigned asbase = smem_u32(As);
    const int tile0 = blockIdx.y * TPS;
    const int tile1 = min(tile0 + TPS, TILES);

    float rmax[8];
    #pragma unroll
    for (int i = 0; i < 8; i++) rmax[i] = __int_as_float(0xff800000);

    for (int ti = tile0; ti < tile1; ++ti) {
        const int c0 = ti * BN;

        float acc[4][4][4];
        #pragma unroll
        for (int mt = 0; mt < 4; mt++)
            #pragma unroll
            for (int nt = 0; nt < 4; nt++)
                #pragma unroll
                for (int j = 0; j < 4; j++) acc[mt][nt][j] = 0.f;

        unsigned b[4][2], bn[4][2];
        loadB(b, c0, 0, nwarp, lane);

        #pragma unroll
        for (int ks = 0; ks < 9; ks++) {
            if (ks < 8) loadB(bn, c0, ks + 1, nwarp, lane);
            unsigned a[4][4];
            #pragma unroll
            for (int mt = 0; mt < 4; mt++) {
                unsigned arow = mwarp * 64 + mt * 16 + (lane & 15);
                unsigned abyte = (arow * ASTRIDE + ks * 16 + (lane >> 4) * 8) * 2;
                ldsm4(a[mt], asbase + abyte);
            }
            #pragma unroll
            for (int mt = 0; mt < 4; mt++)
                #pragma unroll
                for (int nt = 0; nt < 4; nt++)
                    mma16816(acc[mt][nt], a[mt], b[nt]);
            #pragma unroll
            for (int nt = 0; nt < 4; nt++) {
                b[nt][0] = bn[nt][0]; b[nt][1] = bn[nt][1];
            }
        }

        // Epilogue: update per-row running max, pool across the 4 lanes that
        // share each row, THEN capture with the pooled (tighter) threshold.
        #pragma unroll
        for (int mt = 0; mt < 4; mt++)
            #pragma unroll
            for (int nt = 0; nt < 4; nt++)
                #pragma unroll
                for (int j = 0; j < 4; j++) {
                    int h = j >> 1;
                    rmax[mt * 2 + h] = fmaxf(rmax[mt * 2 + h], acc[mt][nt][j]);
                }
        #pragma unroll
        for (int i = 0; i < 8; i++) {
            float o = __shfl_xor_sync(0xFFFFFFFFu, rmax[i], 1);
            rmax[i] = fmaxf(rmax[i], o);
            o = __shfl_xor_sync(0xFFFFFFFFu, rmax[i], 2);
            rmax[i] = fmaxf(rmax[i], o);
        }
        #pragma unroll
        for (int mt = 0; mt < 4; mt++)
            #pragma unroll
            for (int nt = 0; nt < 4; nt++)
                #pragma unroll
                for (int j = 0; j < 4; j++) {
                    int h = j >> 1;
                    float v = acc[mt][nt][j];
                    if (v >= rmax[mt * 2 + h] - CAPW) {
                        int c = c0 + nwarp * 32 + nt * 8 + (lane & 3) * 2 + (j & 1);
                        if (c < NCODES) {
                            int r = row0 + mwarp * 64 + mt * 16 + (lane >> 2) + h * 8;
                            int p = atomicAdd(&g_cnt[r], 1);
                            if (p < CAP) g_cand[(size_t)r * CAP + p] = (unsigned)c;
                        }
                    }
                }
    }
}

// ===========================================================================
// Kernel 3: exact fp32 rescore (bit-identical to R2 scoring semantics)
// ===========================================================================
__global__ void rescore_kernel(const float* __restrict__ z,
                               const float* __restrict__ emb) {
    const int row = blockIdx.x;
    __shared__ float zs[D];
    for (int k = threadIdx.x; k < D; k += 64) zs[k] = z[(size_t)row * D + k];
    __syncthreads();
    const float zn = g_zn[row];
    const int cnt = min(g_cnt[row], CAP);
    for (int i = threadIdx.x; i < cnt; i += 64) {
        unsigned c = g_cand[(size_t)row * CAP + i];
        const float4* e = (const float4*)(emb + (size_t)c * D);
        float acc = 0.f;
        #pragma unroll
        for (int q = 0; q < 36; q++) {
            float4 ev = e[q];
            acc = __fmaf_rn(zs[q * 4 + 0], ev.x, acc);
            acc = __fmaf_rn(zs[q * 4 + 1], ev.y, acc);
            acc = __fmaf_rn(zs[q * 4 + 2], ev.z, acc);
            acc = __fmaf_rn(zs[q * 4 + 3], ev.w, acc);
        }
        float t = __fadd_rn(zn, g_nrm[c]);
        float s = __fmaf_rn(acc, -2.f, t);
        unsigned long long key = ((unsigned long long)ordered_bits(s) << 32) | c;
        atomicMin(&g_best[row], key);
    }
}

// ===========================================================================
// Kernel 4: gather z_q, index, per-row squared-error partial
// ===========================================================================
__global__ void gather_kernel(const float* __restrict__ z,
                              const float* __restrict__ emb,
                              float* __restrict__ out) {
    const int row = blockIdx.x;
    const int tid = threadIdx.x;
    const unsigned idx = (unsigned)(g_best[row] & 0xFFFFFFFFull);
    const float* e  = emb + (size_t)idx * D;
    const float* zr = z + (size_t)row * D;
    float* o = out + (size_t)row * D;

    float s = 0.f;
    for (int d = tid; d < D; d += 128) {
        float q = e[d];
        o[d] = q;
        float df = q - zr[d];
        s += df * df;
    }
    #pragma unroll
    for (int off = 16; off >= 1; off >>= 1)
        s += __shfl_xor_sync(0xFFFFFFFFu, s, off);
    __shared__ float ws[4];
    if ((tid & 31) == 0) ws[tid >> 5] = s;
    __syncthreads();
    if (tid == 0) {
        g_part[row] = ws[0] + ws[1] + ws[2] + ws[3];
        out[ZQ_ELEMS + row] = (float)idx;
    }
}

// ===========================================================================
// Kernel 5: loss (deterministic reduction)
// ===========================================================================
__global__ void finalize_kernel(float* __restrict__ out, int out_size) {
    __shared__ float sh[256];
    float s = 0.f;
    for (int i = threadIdx.x; i < NROWS; i += 256) s += g_part[i];
    sh[threadIdx.x] = s;
    __syncthreads();
    for (int off = 128; off >= 1; off >>= 1) {
        if (threadIdx.x < off) sh[threadIdx.x] += sh[threadIdx.x + off];
        __syncthreads();
    }
    if (threadIdx.x == 0)
        out[out_size - 1] = sh[0] / (float)(ZQ_ELEMS);
}

// ===========================================================================
extern "C" void kernel_launch(void* const* d_in, const int* in_sizes, int n_in,
                              void* d_out, int out_size) {
    const float* z   = (const float*)d_in[0];
    const float* emb = (const float*)d_in[1];
    float* out = (float*)d_out;

    prep_kernel<<<(NCODES + 255) / 256, 256>>>(z, emb);
    screen_kernel<<<dim3(NROWS / BM, NSPLIT), 256>>>(z);
    rescore_kernel<<<NROWS, 64>>>(z, emb);
    gather_kernel<<<NROWS, 128>>>(z, emb, out);
    finalize_kernel<<<1, 256>>>(out, out_size);
}

// round 12
// speedup vs baseline: 1.3482x; 1.1252x over previous
#include <cuda_runtime.h>
#include <cuda_fp16.h>
#include <cstdint>

// ===========================================================================
// Problem constants
// ===========================================================================
#define D        144
#define NROWS    4096
#define NCODES   50257
#define ZQ_ELEMS (NROWS * D)

#define BM       128                        // rows per CTA
#define BN       128                        // codes per tile iteration
#define TILES    ((NCODES + BN - 1) / BN)   // 393
#define NSPLIT   9
#define TPS      ((TILES + NSPLIT - 1) / NSPLIT) // 44

#define CAP      2048                       // candidate slots per row
#define ESCALE   1024.0f                    // emb pre-scale (fp16 normal range)
#define CAPW     (3e-5f * ESCALE)           // capture window, scaled dot units
#define ASTRIDE  152                        // A smem row stride (fp16 elems)

// ===========================================================================
// Global scratch (device globals only — no cudaMalloc)
// ===========================================================================
__device__ unsigned long long g_best[NROWS];
__device__ float    g_nrm[NCODES];
__device__ float    g_zn[NROWS];
__device__ float    g_part[NROWS];
__device__ int      g_cnt[NROWS];
__device__ unsigned g_cand[(size_t)NROWS * CAP];
__device__ __align__(16) __half g_embh[(size_t)NCODES * D];

__device__ __forceinline__ unsigned ordered_bits(float s) {
    unsigned b = __float_as_uint(s);
    return b ^ ((unsigned)((int)b >> 31) | 0x80000000u);
}
__device__ __forceinline__ unsigned pack_h2(float lo, float hi) {
    __half2 h = __floats2half2_rn(lo, hi);
    return *(unsigned*)&h;
}
__device__ __forceinline__ uint32_t smem_u32(const void* p) {
    uint32_t a;
    asm("{ .reg .u64 t; cvta.to.shared.u64 t, %1; cvt.u32.u64 %0, t; }"
        : "=r"(a) : "l"(p));
    return a;
}
__device__ __forceinline__ void ldsm4(unsigned a[4], unsigned addr) {
    asm volatile("ldmatrix.sync.aligned.m8n8.x4.shared.b16 {%0,%1,%2,%3}, [%4];"
                 : "=r"(a[0]), "=r"(a[1]), "=r"(a[2]), "=r"(a[3]) : "r"(addr));
}
// fp16-accumulate HMMA: C/D are 2 regs (each .f16x2)
__device__ __forceinline__ void mma16816h(unsigned c[2], const unsigned a[4],
                                          const unsigned b0, const unsigned b1) {
    asm volatile(
        "mma.sync.aligned.m16n8k16.row.col.f16.f16.f16.f16 "
        "{%0,%1}, {%2,%3,%4,%5}, {%6,%7}, {%0,%1};"
        : "+r"(c[0]), "+r"(c[1])
        : "r"(a[0]), "r"(a[1]), "r"(a[2]), "r"(a[3]), "r"(b0), "r"(b1));
}

// ===========================================================================
// Kernel 1: norms, scaled-fp16 emb copy, scratch reset
// (norm arithmetic bit-identical to the R2/R4-passing kernels)
// ===========================================================================
__global__ void prep_kernel(const float* __restrict__ z,
                            const float* __restrict__ emb) {
    int t = blockIdx.x * 256 + threadIdx.x;
    if (t < NROWS) {
        g_best[t] = 0xFFFFFFFFFFFFFFFFull;
        g_cnt[t] = 0;
        const float4* p = (const float4*)(z + (size_t)t * D);
        float s = 0.f;
        #pragma unroll
        for (int i = 0; i < 36; i++) {
            float4 v = p[i];
            s += v.x * v.x + v.y * v.y + v.z * v.z + v.w * v.w;
        }
        g_zn[t] = s;
    }
    if (t < NCODES) {
        const float4* p = (const float4*)(emb + (size_t)t * D);
        uint2* dst = (uint2*)(g_embh + (size_t)t * D);
        float s = 0.f;
        #pragma unroll
        for (int i = 0; i < 36; i++) {
            float4 v = p[i];
            s += v.x * v.x + v.y * v.y + v.z * v.z + v.w * v.w;
            dst[i] = make_uint2(pack_h2(v.x * ESCALE, v.y * ESCALE),
                                pack_h2(v.z * ESCALE, v.w * ESCALE));
        }
        g_nrm[t] = s;
    }
}

// ===========================================================================
// Kernel 2: fp16 mma.sync screening — barrier-free mainloop (R4 structure)
// grid(32, 9), 256 threads (warps 2m x 4n, warp tile 64x32), 2 CTAs/SM
// ===========================================================================
__device__ __forceinline__ void loadB(unsigned b[4][2], int c0, int ks,
                                      int nwarp, int lane) {
    #pragma unroll
    for (int nt = 0; nt < 4; nt++) {
        int code = c0 + nwarp * 32 + nt * 8 + (lane >> 2);
        if (code < NCODES) {
            const __half* p =
                g_embh + (size_t)code * D + ks * 16 + (lane & 3) * 2;
            b[nt][0] = *(const unsigned*)p;
            b[nt][1] = *(const unsigned*)(p + 8);
        } else {
            b[nt][0] = 0u; b[nt][1] = 0u;
        }
    }
}

__global__ void __launch_bounds__(256, 2)
screen_kernel(const float* __restrict__ z) {
    __shared__ __half As[BM * ASTRIDE];

    const int tid  = threadIdx.x;
    const int lane = tid & 31;
    const int wid  = tid >> 5;
    const int mwarp = wid >> 2;       // 0..1
    const int nwarp = wid & 3;        // 0..3
    const int row0 = blockIdx.x * BM;

    // Load z tile -> fp16 smem (row-major, stride 152). 2 threads per row.
    {
        int row = tid >> 1, half = tid & 1;
        const float4* src = (const float4*)(z + (size_t)(row0 + row) * D + half * 72);
        unsigned eo = row * ASTRIDE + half * 72;
        #pragma unroll
        for (int j = 0; j < 18; j++) {
            float4 v = src[j];
            *(uint2*)(As + eo + j * 4) =
                make_uint2(pack_h2(v.x, v.y), pack_h2(v.z, v.w));
        }
    }
    __syncthreads();

    const unsigned asbase = smem_u32(As);
    const int tile0 = blockIdx.y * TPS;
    const int tile1 = min(tile0 + TPS, TILES);

    float rmax[8];
    #pragma unroll
    for (int i = 0; i < 8; i++) rmax[i] = __int_as_float(0xff800000);

    for (int ti = tile0; ti < tile1; ++ti) {
        const int c0 = ti * BN;

        unsigned acc[4][4][2];
        #pragma unroll
        for (int mt = 0; mt < 4; mt++)
            #pragma unroll
            for (int nt = 0; nt < 4; nt++) {
                acc[mt][nt][0] = 0u; acc[mt][nt][1] = 0u;  // half2 zeros
            }

        unsigned b[4][2], bn[4][2];
        loadB(b, c0, 0, nwarp, lane);

        #pragma unroll
        for (int ks = 0; ks < 9; ks++) {
            if (ks < 8) loadB(bn, c0, ks + 1, nwarp, lane);
            unsigned a[4][4];
            #pragma unroll
            for (int mt = 0; mt < 4; mt++) {
                unsigned arow = mwarp * 64 + mt * 16 + (lane & 15);
                unsigned abyte = (arow * ASTRIDE + ks * 16 + (lane >> 4) * 8) * 2;
                ldsm4(a[mt], asbase + abyte);
            }
            #pragma unroll
            for (int mt = 0; mt < 4; mt++)
                #pragma unroll
                for (int nt = 0; nt < 4; nt++)
                    mma16816h(acc[mt][nt], a[mt], b[nt][0], b[nt][1]);
            #pragma unroll
            for (int nt = 0; nt < 4; nt++) {
                b[nt][0] = bn[nt][0]; b[nt][1] = bn[nt][1];
            }
        }

        // Epilogue (R4 order): per-lane running-max update + capture, then pool.
        // f16 C layout: reg h: row = lane>>2 + 8h; cols = (lane&3)*2 + {0,1}.
        #pragma unroll
        for (int mt = 0; mt < 4; mt++) {
            float vf[4][2][2];
            #pragma unroll
            for (int nt = 0; nt < 4; nt++)
                #pragma unroll
                for (int h = 0; h < 2; h++) {
                    __half2 hv = *(__half2*)&acc[mt][nt][h];
                    float2 f = __half22float2(hv);
                    vf[nt][h][0] = f.x;
                    vf[nt][h][1] = f.y;
                    rmax[mt * 2 + h] = fmaxf(rmax[mt * 2 + h], fmaxf(f.x, f.y));
                }
            #pragma unroll
            for (int nt = 0; nt < 4; nt++)
                #pragma unroll
                for (int h = 0; h < 2; h++)
                    #pragma unroll
                    for (int q = 0; q < 2; q++) {
                        float v = vf[nt][h][q];
                        if (v >= rmax[mt * 2 + h] - CAPW) {
                            int c = c0 + nwarp * 32 + nt * 8 + (lane & 3) * 2 + q;
                            if (c < NCODES) {
                                int r = row0 + mwarp * 64 + mt * 16 + (lane >> 2) + h * 8;
                                int p = atomicAdd(&g_cnt[r], 1);
                                if (p < CAP) g_cand[(size_t)r * CAP + p] = (unsigned)c;
                            }
                        }
                    }
        }
        // Pool rmax across the 4 lanes that share each row
        #pragma unroll
        for (int i = 0; i < 8; i++) {
            float o = __shfl_xor_sync(0xFFFFFFFFu, rmax[i], 1);
            rmax[i] = fmaxf(rmax[i], o);
            o = __shfl_xor_sync(0xFFFFFFFFu, rmax[i], 2);
            rmax[i] = fmaxf(rmax[i], o);
        }
    }
}

// ===========================================================================
// Kernel 3: exact fp32 rescore (bit-identical to R2 scoring semantics)
// ===========================================================================
__global__ void rescore_kernel(const float* __restrict__ z,
                               const float* __restrict__ emb) {
    const int row = blockIdx.x;
    __shared__ float zs[D];
    for (int k = threadIdx.x; k < D; k += 64) zs[k] = z[(size_t)row * D + k];
    __syncthreads();
    const float zn = g_zn[row];
    const int cnt = min(g_cnt[row], CAP);
    for (int i = threadIdx.x; i < cnt; i += 64) {
        unsigned c = g_cand[(size_t)row * CAP + i];
        const float4* e = (const float4*)(emb + (size_t)c * D);
        float acc = 0.f;
        #pragma unroll
        for (int q = 0; q < 36; q++) {
            float4 ev = e[q];
            acc = __fmaf_rn(zs[q * 4 + 0], ev.x, acc);
            acc = __fmaf_rn(zs[q * 4 + 1], ev.y, acc);
            acc = __fmaf_rn(zs[q * 4 + 2], ev.z, acc);
            acc = __fmaf_rn(zs[q * 4 + 3], ev.w, acc);
        }
        float t = __fadd_rn(zn, g_nrm[c]);
        float s = __fmaf_rn(acc, -2.f, t);
        unsigned long long key = ((unsigned long long)ordered_bits(s) << 32) | c;
        atomicMin(&g_best[row], key);
    }
}

// ===========================================================================
// Kernel 4: gather z_q, index, per-row squared-error partial
// ===========================================================================
__global__ void gather_kernel(const float* __restrict__ z,
                              const float* __restrict__ emb,
                              float* __restrict__ out) {
    const int row = blockIdx.x;
    const int tid = threadIdx.x;
    unsigned idx = (unsigned)(g_best[row] & 0xFFFFFFFFull);
    if (idx >= NCODES) idx = 0;   // defensive (no-op when capture is sound)
    const float* e  = emb + (size_t)idx * D;
    const float* zr = z + (size_t)row * D;
    float* o = out + (size_t)row * D;

    float s = 0.f;
    for (int d = tid; d < D; d += 128) {
        float q = e[d];
        o[d] = q;
        float df = q - zr[d];
        s += df * df;
    }
    #pragma unroll
    for (int off = 16; off >= 1; off >>= 1)
        s += __shfl_xor_sync(0xFFFFFFFFu, s, off);
    __shared__ float ws[4];
    if ((tid & 31) == 0) ws[tid >> 5] = s;
    __syncthreads();
    if (tid == 0) {
        g_part[row] = ws[0] + ws[1] + ws[2] + ws[3];
        out[ZQ_ELEMS + row] = (float)idx;
    }
}

// ===========================================================================
// Kernel 5: loss (deterministic reduction)
// ===========================================================================
__global__ void finalize_kernel(float* __restrict__ out, int out_size) {
    __shared__ float sh[256];
    float s = 0.f;
    for (int i = threadIdx.x; i < NROWS; i += 256) s += g_part[i];
    sh[threadIdx.x] = s;
    __syncthreads();
    for (int off = 128; off >= 1; off >>= 1) {
        if (threadIdx.x < off) sh[threadIdx.x] += sh[threadIdx.x + off];
        __syncthreads();
    }
    if (threadIdx.x == 0)
        out[out_size - 1] = sh[0] / (float)(ZQ_ELEMS);
}

// ===========================================================================
extern "C" void kernel_launch(void* const* d_in, const int* in_sizes, int n_in,
                              void* d_out, int out_size) {
    const float* z   = (const float*)d_in[0];
    const float* emb = (const float*)d_in[1];
    float* out = (float*)d_out;

    prep_kernel<<<(NCODES + 255) / 256, 256>>>(z, emb);
    screen_kernel<<<dim3(NROWS / BM, NSPLIT), 256>>>(z);
    rescore_kernel<<<NROWS, 64>>>(z, emb);
    gather_kernel<<<NROWS, 128>>>(z, emb, out);
    finalize_kernel<<<1, 256>>>(out, out_size);
}